// round 15
// baseline (speedup 1.0000x reference)
#include <cuda_runtime.h>
#include <cstring>

#define K_DIM   64
#define TILE    128
#define XT_STR  132   // padded stride (multiple of 4 for aligned float4, breaks bank conflicts)

#define MAX_AGENTS 50000

// Scratch: per-agent pooled features (segment_sum output). Static device array
// (no cudaMalloc allowed anywhere).
__device__ float g_summ[MAX_AGENTS * K_DIM];

// Packed dual-FMA (Blackwell f32x2): two independent fp32 FMAs per instruction.
__device__ __forceinline__ float2 ffma2(float2 a, float2 b, float2 c) {
    unsigned long long au, bu, cu, du;
    memcpy(&au, &a, 8); memcpy(&bu, &b, 8); memcpy(&cu, &c, 8);
    asm("fma.rn.f32x2 %0, %1, %2, %3;" : "=l"(du) : "l"(au), "l"(bu), "l"(cu));
    float2 d; memcpy(&d, &du, 8); return d;
}

__global__ void zero_kernel(int n4) {
    int i = blockIdx.x * blockDim.x + threadIdx.x;
    if (i < n4) {
        reinterpret_cast<float4*>(g_summ)[i] = make_float4(0.f, 0.f, 0.f, 0.f);
    }
}

// ---------------------------------------------------------------------------
// phi kernel: h2 = relu(X @ W1 + b1) @ W2 + b2, then segment-sum into g_summ.
// Tile = 128 rows. 256 threads: thread = 8 rows x 4 cols microtile, rows packed
// into f32x2 pairs. Sorted segment_ids -> per-thread run compression before atomics.
// ---------------------------------------------------------------------------
extern __shared__ float smem_f[];

__global__ __launch_bounds__(256, 2)
void phi_kernel(const float* __restrict__ nb,
                const float* __restrict__ w1, const float* __restrict__ b1,
                const float* __restrict__ w2, const float* __restrict__ b2,
                const int*   __restrict__ seg,
                int nrows)
{
    float* w1s = smem_f;                    // 64*64 = 4096
    float* w2s = w1s + 4096;                // 4096
    float* xT  = w2s + 4096;                // 64*132 = 8448 (transposed: xT[k][row])
    float* hT  = xT  + 64 * XT_STR;         // 8448
    float* b1s = hT  + 64 * XT_STR;         // 64
    float* b2s = b1s + 64;                  // 64
    int*   segs = (int*)(b2s + 64);         // 128

    const int tid = threadIdx.x;

    // Stage weights + biases
    #pragma unroll 4
    for (int i = tid; i < 4096; i += 256) { w1s[i] = w1[i]; w2s[i] = w2[i]; }
    if (tid < 64) { b1s[tid] = b1[tid]; b2s[tid] = b2[tid]; }

    const int base = blockIdx.x * TILE;

    // Load X tile transposed (coalesced gmem float4 reads, strided smem writes)
    const float4* nb4 = reinterpret_cast<const float4*>(nb + (long long)base * K_DIM);
    #pragma unroll
    for (int i = tid; i < TILE * K_DIM / 4; i += 256) {
        int idx = i * 4;
        int r = idx >> 6;           // row in tile
        int c = idx & 63;           // first of 4 columns
        float4 v = (base + r < nrows) ? nb4[i] : make_float4(0.f, 0.f, 0.f, 0.f);
        xT[(c + 0) * XT_STR + r] = v.x;
        xT[(c + 1) * XT_STR + r] = v.y;
        xT[(c + 2) * XT_STR + r] = v.z;
        xT[(c + 3) * XT_STR + r] = v.w;
    }
    if (tid < TILE) segs[tid] = (base + tid < nrows) ? seg[base + tid] : -1;
    __syncthreads();

    const int tx = tid & 15;        // col group: 4 cols
    const int ty = tid >> 4;        // row group: 8 rows
    const int row0 = ty * 8;
    const int col0 = tx * 4;

    float2 acc[4][4];               // acc[p][c]: rows (row0+2p, row0+2p+1), col col0+c

    // ---- Layer 1 ----
    #pragma unroll
    for (int c = 0; c < 4; c++) {
        float bv = b1s[col0 + c];
        #pragma unroll
        for (int p = 0; p < 4; p++) acc[p][c] = make_float2(bv, bv);
    }
    #pragma unroll 4
    for (int k = 0; k < K_DIM; k++) {
        float4 a0 = *reinterpret_cast<const float4*>(&xT[k * XT_STR + row0]);
        float4 a1 = *reinterpret_cast<const float4*>(&xT[k * XT_STR + row0 + 4]);
        float4 wv = *reinterpret_cast<const float4*>(&w1s[k * K_DIM + col0]);
        float2 pr[4] = { make_float2(a0.x, a0.y), make_float2(a0.z, a0.w),
                         make_float2(a1.x, a1.y), make_float2(a1.z, a1.w) };
        float wa[4] = { wv.x, wv.y, wv.z, wv.w };
        #pragma unroll
        for (int c = 0; c < 4; c++) {
            float2 wb = make_float2(wa[c], wa[c]);
            #pragma unroll
            for (int p = 0; p < 4; p++) acc[p][c] = ffma2(pr[p], wb, acc[p][c]);
        }
    }
    // relu -> hT (transposed, float2 stores of row pairs)
    #pragma unroll
    for (int c = 0; c < 4; c++) {
        #pragma unroll
        for (int p = 0; p < 4; p++) {
            float2 v = acc[p][c];
            v.x = fmaxf(v.x, 0.f); v.y = fmaxf(v.y, 0.f);
            *reinterpret_cast<float2*>(&hT[(col0 + c) * XT_STR + row0 + 2 * p]) = v;
        }
    }
    __syncthreads();

    // ---- Layer 2 ----
    #pragma unroll
    for (int c = 0; c < 4; c++) {
        float bv = b2s[col0 + c];
        #pragma unroll
        for (int p = 0; p < 4; p++) acc[p][c] = make_float2(bv, bv);
    }
    #pragma unroll 4
    for (int k = 0; k < K_DIM; k++) {
        float4 a0 = *reinterpret_cast<const float4*>(&hT[k * XT_STR + row0]);
        float4 a1 = *reinterpret_cast<const float4*>(&hT[k * XT_STR + row0 + 4]);
        float4 wv = *reinterpret_cast<const float4*>(&w2s[k * K_DIM + col0]);
        float2 pr[4] = { make_float2(a0.x, a0.y), make_float2(a0.z, a0.w),
                         make_float2(a1.x, a1.y), make_float2(a1.z, a1.w) };
        float wa[4] = { wv.x, wv.y, wv.z, wv.w };
        #pragma unroll
        for (int c = 0; c < 4; c++) {
            float2 wb = make_float2(wa[c], wa[c]);
            #pragma unroll
            for (int p = 0; p < 4; p++) acc[p][c] = ffma2(pr[p], wb, acc[p][c]);
        }
    }

    // ---- Segment reduction epilogue ----
    // segment_ids sorted -> each thread's 8 contiguous rows form few runs.
    const int grow = base + row0;
    int cur = -1;
    float s0 = 0.f, s1 = 0.f, s2 = 0.f, s3 = 0.f;
    #pragma unroll
    for (int i = 0; i < 8; i++) {
        if (grow + i >= nrows) break;
        int sid = segs[row0 + i];
        int p = i >> 1;
        float v0, v1, v2, v3;
        if (i & 1) { v0 = acc[p][0].y; v1 = acc[p][1].y; v2 = acc[p][2].y; v3 = acc[p][3].y; }
        else       { v0 = acc[p][0].x; v1 = acc[p][1].x; v2 = acc[p][2].x; v3 = acc[p][3].x; }
        if (sid == cur) { s0 += v0; s1 += v1; s2 += v2; s3 += v3; }
        else {
            if (cur >= 0) {
                float* dst = &g_summ[cur * K_DIM + col0];
                atomicAdd(dst + 0, s0); atomicAdd(dst + 1, s1);
                atomicAdd(dst + 2, s2); atomicAdd(dst + 3, s3);
            }
            cur = sid; s0 = v0; s1 = v1; s2 = v2; s3 = v3;
        }
    }
    if (cur >= 0) {
        float* dst = &g_summ[cur * K_DIM + col0];
        atomicAdd(dst + 0, s0); atomicAdd(dst + 1, s1);
        atomicAdd(dst + 2, s2); atomicAdd(dst + 3, s3);
    }
}

// ---------------------------------------------------------------------------
// rho kernel: out = relu(summ @ rho_w1 + rho_b1) @ rho_w2 + rho_b2
// ---------------------------------------------------------------------------
__global__ __launch_bounds__(256, 2)
void rho_kernel(const float* __restrict__ w1, const float* __restrict__ b1,
                const float* __restrict__ w2, const float* __restrict__ b2,
                float* __restrict__ out, int nAgents)
{
    float* w1s = smem_f;                    // 4096
    float* xT  = w1s + 4096;                // 8448
    float* hT  = xT  + 64 * XT_STR;         // 8448
    float* b1s = hT  + 64 * XT_STR;         // 64
    float* w2b = b1s + 64;                  // 128 (64x2)
    float* b2b = w2b + 128;                 // 2

    const int tid = threadIdx.x;

    #pragma unroll 4
    for (int i = tid; i < 4096; i += 256) w1s[i] = w1[i];
    if (tid < 64)  b1s[tid] = b1[tid];
    if (tid < 128) w2b[tid] = w2[tid];
    if (tid < 2)   b2b[tid] = b2[tid];

    const int base = blockIdx.x * TILE;

    const float4* x4 = reinterpret_cast<const float4*>(g_summ + (long long)base * K_DIM);
    #pragma unroll
    for (int i = tid; i < TILE * K_DIM / 4; i += 256) {
        int idx = i * 4;
        int r = idx >> 6;
        int c = idx & 63;
        float4 v = (base + r < nAgents) ? x4[i] : make_float4(0.f, 0.f, 0.f, 0.f);
        xT[(c + 0) * XT_STR + r] = v.x;
        xT[(c + 1) * XT_STR + r] = v.y;
        xT[(c + 2) * XT_STR + r] = v.z;
        xT[(c + 3) * XT_STR + r] = v.w;
    }
    __syncthreads();

    const int tx = tid & 15;
    const int ty = tid >> 4;
    const int row0 = ty * 8;
    const int col0 = tx * 4;

    float2 acc[4][4];
    #pragma unroll
    for (int c = 0; c < 4; c++) {
        float bv = b1s[col0 + c];
        #pragma unroll
        for (int p = 0; p < 4; p++) acc[p][c] = make_float2(bv, bv);
    }
    #pragma unroll 4
    for (int k = 0; k < K_DIM; k++) {
        float4 a0 = *reinterpret_cast<const float4*>(&xT[k * XT_STR + row0]);
        float4 a1 = *reinterpret_cast<const float4*>(&xT[k * XT_STR + row0 + 4]);
        float4 wv = *reinterpret_cast<const float4*>(&w1s[k * K_DIM + col0]);
        float2 pr[4] = { make_float2(a0.x, a0.y), make_float2(a0.z, a0.w),
                         make_float2(a1.x, a1.y), make_float2(a1.z, a1.w) };
        float wa[4] = { wv.x, wv.y, wv.z, wv.w };
        #pragma unroll
        for (int c = 0; c < 4; c++) {
            float2 wb = make_float2(wa[c], wa[c]);
            #pragma unroll
            for (int p = 0; p < 4; p++) acc[p][c] = ffma2(pr[p], wb, acc[p][c]);
        }
    }
    // relu -> hT
    #pragma unroll
    for (int c = 0; c < 4; c++) {
        #pragma unroll
        for (int p = 0; p < 4; p++) {
            float2 v = acc[p][c];
            v.x = fmaxf(v.x, 0.f); v.y = fmaxf(v.y, 0.f);
            *reinterpret_cast<float2*>(&hT[(col0 + c) * XT_STR + row0 + 2 * p]) = v;
        }
    }
    __syncthreads();

    // Layer 2: 64 -> 2. One output element per thread (128 rows x 2 cols = 256).
    int r = tid >> 1;
    int c = tid & 1;
    if (base + r < nAgents) {
        float s = b2b[c];
        #pragma unroll 8
        for (int k = 0; k < K_DIM; k++) {
            s = fmaf(hT[k * XT_STR + r], w2b[k * 2 + c], s);
        }
        out[(base + r) * 2 + c] = s;
    }
}

// ---------------------------------------------------------------------------
extern "C" void kernel_launch(void* const* d_in, const int* in_sizes, int n_in,
                              void* d_out, int out_size)
{
    const float* neighbors = (const float*)d_in[0];
    const float* phi_w1    = (const float*)d_in[1];
    const float* phi_b1    = (const float*)d_in[2];
    const float* phi_w2    = (const float*)d_in[3];
    const float* phi_b2    = (const float*)d_in[4];
    const float* rho_w1    = (const float*)d_in[5];
    const float* rho_b1    = (const float*)d_in[6];
    const float* rho_w2    = (const float*)d_in[7];
    const float* rho_b2    = (const float*)d_in[8];
    const int*   seg       = (const int*)d_in[9];
    float* out = (float*)d_out;

    const int nN = in_sizes[9];        // N_NEIGHBORS (count of segment_ids)
    const int nA = out_size / 2;       // N_AGENTS

    const int PHI_SMEM = (4096 + 4096 + 64 * XT_STR + 64 * XT_STR + 64 + 64) * 4 + TILE * 4; // 101376
    const int RHO_SMEM = (4096 + 64 * XT_STR + 64 * XT_STR + 64 + 128 + 2) * 4;              // 84744

    cudaFuncSetAttribute(phi_kernel, cudaFuncAttributeMaxDynamicSharedMemorySize, PHI_SMEM);
    cudaFuncSetAttribute(rho_kernel, cudaFuncAttributeMaxDynamicSharedMemorySize, RHO_SMEM);

    // 1) zero the segment-sum scratch (full static buffer)
    const int n4 = MAX_AGENTS * K_DIM / 4;
    zero_kernel<<<(n4 + 255) / 256, 256>>>(n4);

    // 2) phi MLP + segment sum
    const int phi_blocks = (nN + TILE - 1) / TILE;
    phi_kernel<<<phi_blocks, 256, PHI_SMEM>>>(neighbors, phi_w1, phi_b1, phi_w2, phi_b2, seg, nN);

    // 3) rho MLP
    const int rho_blocks = (nA + TILE - 1) / TILE;
    rho_kernel<<<rho_blocks, 256, RHO_SMEM>>>(rho_w1, rho_b1, rho_w2, rho_b2, out, nA);
}

// round 16
// speedup vs baseline: 1.1650x; 1.1650x over previous
#include <cuda_runtime.h>
#include <cstring>

#define K_DIM   64
#define TILE    128
#define XT_STR  132   // 33 x 16B units per column

#define MAX_AGENTS 50000

// Scratch: per-agent pooled features (segment_sum output).
__device__ float g_summ[MAX_AGENTS * K_DIM];

// Packed dual-FMA (Blackwell f32x2).
__device__ __forceinline__ float2 ffma2(float2 a, float2 b, float2 c) {
    unsigned long long au, bu, cu, du;
    memcpy(&au, &a, 8); memcpy(&bu, &b, 8); memcpy(&cu, &c, 8);
    asm("fma.rn.f32x2 %0, %1, %2, %3;" : "=l"(du) : "l"(au), "l"(bu), "l"(cu));
    float2 d; memcpy(&d, &du, 8); return d;
}

// Swizzled transposed-tile addressing: column c, 16B row-unit ru (0..31).
// float offset of the 16B unit start:
__device__ __forceinline__ int sw_off(int c, int ru) {
    return c * XT_STR + (((ru) ^ ((c >> 2) & 7)) << 2);
}

__global__ void zero_kernel(int n4) {
    int i = blockIdx.x * blockDim.x + threadIdx.x;
    if (i < n4) {
        reinterpret_cast<float4*>(g_summ)[i] = make_float4(0.f, 0.f, 0.f, 0.f);
    }
}

extern __shared__ float smem_f[];

// ---------------------------------------------------------------------------
// Load a 128x64 tile from src (row-major, rows base..base+127, guard nrows)
// into transposed+swizzled smem tile tT. 256 threads.
// Thread handles 2 sub-blocks of 4 rows x 4 cols: register transpose,
// conflict-free STS.128 along rows.
// ---------------------------------------------------------------------------
__device__ __forceinline__ void load_tile_T(const float* __restrict__ src,
                                            float* tT, int base, int nrows, int tid)
{
    const float4* s4 = reinterpret_cast<const float4*>(src + (long long)base * K_DIM);
    const int b = tid & 15;          // col group: cols 4b..4b+3
    #pragma unroll
    for (int it = 0; it < 2; it++) {
        const int a = ((tid >> 4) << 1) + it;   // row group: rows 4a..4a+3 (0..31)
        const int grow = base + 4 * a;
        float r[4][4];
        #pragma unroll
        for (int i = 0; i < 4; i++) {
            float4 v = (grow + i < nrows) ? s4[(4 * a + i) * 16 + b]
                                          : make_float4(0.f, 0.f, 0.f, 0.f);
            r[i][0] = v.x; r[i][1] = v.y; r[i][2] = v.z; r[i][3] = v.w;
        }
        #pragma unroll
        for (int j = 0; j < 4; j++) {
            const int c = 4 * b + j;
            float4 v = make_float4(r[0][j], r[1][j], r[2][j], r[3][j]);
            *reinterpret_cast<float4*>(&tT[sw_off(c, a)]) = v;
        }
    }
}

// One 128x64 @ 64x64 microtile pass: acc[p][c] covers rows (row0+2p, row0+2p+1),
// col col0+c. xT is swizzled-transposed, w is row-major [64][64].
__device__ __forceinline__ void mma_tile(const float* xT, const float* w,
                                         int ty, int tx, float2 acc[4][4])
{
    const int col0 = tx * 4;
    #pragma unroll 4
    for (int k = 0; k < K_DIM; k++) {
        const int sk = (k >> 2) & 7;
        float4 a0 = *reinterpret_cast<const float4*>(&xT[k * XT_STR + (((2 * ty)     ^ sk) << 2)]);
        float4 a1 = *reinterpret_cast<const float4*>(&xT[k * XT_STR + (((2 * ty + 1) ^ sk) << 2)]);
        float4 wv = *reinterpret_cast<const float4*>(&w[k * K_DIM + col0]);
        float2 pr[4] = { make_float2(a0.x, a0.y), make_float2(a0.z, a0.w),
                         make_float2(a1.x, a1.y), make_float2(a1.z, a1.w) };
        float wa[4] = { wv.x, wv.y, wv.z, wv.w };
        #pragma unroll
        for (int c = 0; c < 4; c++) {
            float2 wb = make_float2(wa[c], wa[c]);
            #pragma unroll
            for (int p = 0; p < 4; p++) acc[p][c] = ffma2(pr[p], wb, acc[p][c]);
        }
    }
}

// Store acc (with relu) into swizzled-transposed hT. Thread's 8 consecutive rows
// per column -> 2 conflict-free STS.128 per column.
__device__ __forceinline__ void store_relu_T(float* hT, int ty, int tx, float2 acc[4][4])
{
    const int col0 = tx * 4;
    #pragma unroll
    for (int c = 0; c < 4; c++) {
        const int col = col0 + c;
        float4 lo = make_float4(fmaxf(acc[0][c].x, 0.f), fmaxf(acc[0][c].y, 0.f),
                                fmaxf(acc[1][c].x, 0.f), fmaxf(acc[1][c].y, 0.f));
        float4 hi = make_float4(fmaxf(acc[2][c].x, 0.f), fmaxf(acc[2][c].y, 0.f),
                                fmaxf(acc[3][c].x, 0.f), fmaxf(acc[3][c].y, 0.f));
        *reinterpret_cast<float4*>(&hT[sw_off(col, 2 * ty)])     = lo;
        *reinterpret_cast<float4*>(&hT[sw_off(col, 2 * ty + 1)]) = hi;
    }
}

// ---------------------------------------------------------------------------
// phi kernel: h2 = relu(X @ W1 + b1) @ W2 + b2, segment-sum into g_summ.
// ---------------------------------------------------------------------------
__global__ __launch_bounds__(256, 2)
void phi_kernel(const float* __restrict__ nb,
                const float* __restrict__ w1, const float* __restrict__ b1,
                const float* __restrict__ w2, const float* __restrict__ b2,
                const int*   __restrict__ seg,
                int nrows)
{
    float* w1s = smem_f;                    // 4096
    float* w2s = w1s + 4096;                // 4096
    float* xT  = w2s + 4096;                // 8448
    float* hT  = xT  + 64 * XT_STR;         // 8448
    float* b1s = hT  + 64 * XT_STR;         // 64
    float* b2s = b1s + 64;                  // 64
    int*   segs = (int*)(b2s + 64);         // 128

    const int tid = threadIdx.x;

    #pragma unroll 4
    for (int i = tid; i < 4096; i += 256) { w1s[i] = w1[i]; w2s[i] = w2[i]; }
    if (tid < 64) { b1s[tid] = b1[tid]; b2s[tid] = b2[tid]; }

    const int base = blockIdx.x * TILE;
    load_tile_T(nb, xT, base, nrows, tid);
    if (tid < TILE) segs[tid] = (base + tid < nrows) ? seg[base + tid] : -1;
    __syncthreads();

    const int tx = tid & 15;
    const int ty = tid >> 4;
    const int row0 = ty * 8;
    const int col0 = tx * 4;

    float2 acc[4][4];

    // ---- Layer 1 ----
    #pragma unroll
    for (int c = 0; c < 4; c++) {
        float bv = b1s[col0 + c];
        #pragma unroll
        for (int p = 0; p < 4; p++) acc[p][c] = make_float2(bv, bv);
    }
    mma_tile(xT, w1s, ty, tx, acc);
    store_relu_T(hT, ty, tx, acc);
    __syncthreads();

    // ---- Layer 2 ----
    #pragma unroll
    for (int c = 0; c < 4; c++) {
        float bv = b2s[col0 + c];
        #pragma unroll
        for (int p = 0; p < 4; p++) acc[p][c] = make_float2(bv, bv);
    }
    mma_tile(hT, w2s, ty, tx, acc);

    // ---- Segment reduction epilogue (sorted ids -> run compression) ----
    const int grow = base + row0;
    int cur = -1;
    float s0 = 0.f, s1 = 0.f, s2 = 0.f, s3 = 0.f;
    #pragma unroll
    for (int i = 0; i < 8; i++) {
        if (grow + i >= nrows) break;
        int sid = segs[row0 + i];
        int p = i >> 1;
        float v0, v1, v2, v3;
        if (i & 1) { v0 = acc[p][0].y; v1 = acc[p][1].y; v2 = acc[p][2].y; v3 = acc[p][3].y; }
        else       { v0 = acc[p][0].x; v1 = acc[p][1].x; v2 = acc[p][2].x; v3 = acc[p][3].x; }
        if (sid == cur) { s0 += v0; s1 += v1; s2 += v2; s3 += v3; }
        else {
            if (cur >= 0) {
                float* dst = &g_summ[cur * K_DIM + col0];
                atomicAdd(dst + 0, s0); atomicAdd(dst + 1, s1);
                atomicAdd(dst + 2, s2); atomicAdd(dst + 3, s3);
            }
            cur = sid; s0 = v0; s1 = v1; s2 = v2; s3 = v3;
        }
    }
    if (cur >= 0) {
        float* dst = &g_summ[cur * K_DIM + col0];
        atomicAdd(dst + 0, s0); atomicAdd(dst + 1, s1);
        atomicAdd(dst + 2, s2); atomicAdd(dst + 3, s3);
    }
}

// ---------------------------------------------------------------------------
// rho kernel: out = relu(summ @ rho_w1 + rho_b1) @ rho_w2 + rho_b2
// ---------------------------------------------------------------------------
__global__ __launch_bounds__(256, 2)
void rho_kernel(const float* __restrict__ w1, const float* __restrict__ b1,
                const float* __restrict__ w2, const float* __restrict__ b2,
                float* __restrict__ out, int nAgents)
{
    float* w1s = smem_f;                    // 4096
    float* xT  = w1s + 4096;                // 8448
    float* hT  = xT  + 64 * XT_STR;         // 8448
    float* b1s = hT  + 64 * XT_STR;         // 64
    float* w2b = b1s + 64;                  // 128
    float* b2b = w2b + 128;                 // 2

    const int tid = threadIdx.x;

    #pragma unroll 4
    for (int i = tid; i < 4096; i += 256) w1s[i] = w1[i];
    if (tid < 64)  b1s[tid] = b1[tid];
    if (tid < 128) w2b[tid] = w2[tid];
    if (tid < 2)   b2b[tid] = b2[tid];

    const int base = blockIdx.x * TILE;
    load_tile_T(g_summ, xT, base, nAgents, tid);
    __syncthreads();

    const int tx = tid & 15;
    const int ty = tid >> 4;
    const int col0 = tx * 4;

    float2 acc[4][4];
    #pragma unroll
    for (int c = 0; c < 4; c++) {
        float bv = b1s[col0 + c];
        #pragma unroll
        for (int p = 0; p < 4; p++) acc[p][c] = make_float2(bv, bv);
    }
    mma_tile(xT, w1s, ty, tx, acc);
    store_relu_T(hT, ty, tx, acc);
    __syncthreads();

    // Layer 2: 64 -> 2. One output element per thread.
    int r = tid >> 1;
    int c = tid & 1;
    if (base + r < nAgents) {
        float s = b2b[c];
        #pragma unroll 8
        for (int k = 0; k < K_DIM; k++) {
            int sk = (k >> 2) & 7;
            float hv = hT[k * XT_STR + ((((r >> 2) ^ sk) << 2)) + (r & 3)];
            s = fmaf(hv, w2b[k * 2 + c], s);
        }
        out[(base + r) * 2 + c] = s;
    }
}

// ---------------------------------------------------------------------------
extern "C" void kernel_launch(void* const* d_in, const int* in_sizes, int n_in,
                              void* d_out, int out_size)
{
    const float* neighbors = (const float*)d_in[0];
    const float* phi_w1    = (const float*)d_in[1];
    const float* phi_b1    = (const float*)d_in[2];
    const float* phi_w2    = (const float*)d_in[3];
    const float* phi_b2    = (const float*)d_in[4];
    const float* rho_w1    = (const float*)d_in[5];
    const float* rho_b1    = (const float*)d_in[6];
    const float* rho_w2    = (const float*)d_in[7];
    const float* rho_b2    = (const float*)d_in[8];
    const int*   seg       = (const int*)d_in[9];
    float* out = (float*)d_out;

    const int nN = in_sizes[9];        // N_NEIGHBORS
    const int nA = out_size / 2;       // N_AGENTS

    const int PHI_SMEM = (4096 + 4096 + 64 * XT_STR + 64 * XT_STR + 64 + 64) * 4 + TILE * 4;
    const int RHO_SMEM = (4096 + 64 * XT_STR + 64 * XT_STR + 64 + 128 + 2) * 4;

    cudaFuncSetAttribute(phi_kernel, cudaFuncAttributeMaxDynamicSharedMemorySize, PHI_SMEM);
    cudaFuncSetAttribute(rho_kernel, cudaFuncAttributeMaxDynamicSharedMemorySize, RHO_SMEM);

    const int n4 = MAX_AGENTS * K_DIM / 4;
    zero_kernel<<<(n4 + 255) / 256, 256>>>(n4);

    const int phi_blocks = (nN + TILE - 1) / TILE;
    phi_kernel<<<phi_blocks, 256, PHI_SMEM>>>(neighbors, phi_w1, phi_b1, phi_w2, phi_b2, seg, nN);

    const int rho_blocks = (nA + TILE - 1) / TILE;
    rho_kernel<<<rho_blocks, 256, RHO_SMEM>>>(rho_w1, rho_b1, rho_w2, rho_b2, out, nA);
}

// round 17
// speedup vs baseline: 1.2629x; 1.0841x over previous
#include <cuda_runtime.h>
#include <cstring>

#define K_DIM   64
#define TILE    128
#define XT_STR  132   // rho kernel transposed-tile stride (16B-swizzled)
#define XS_STR  68    // phi: X/H row-major stride (A-frag conflict-free)
#define WS_STR  72    // phi: W stride (B-frag conflict-free)

#define MAX_AGENTS 50000

__device__ float g_summ[MAX_AGENTS * K_DIM];

// ---------------- common helpers ----------------

__device__ __forceinline__ float2 ffma2(float2 a, float2 b, float2 c) {
    unsigned long long au, bu, cu, du;
    memcpy(&au, &a, 8); memcpy(&bu, &b, 8); memcpy(&cu, &c, 8);
    asm("fma.rn.f32x2 %0, %1, %2, %3;" : "=l"(du) : "l"(au), "l"(bu), "l"(cu));
    float2 d; memcpy(&d, &du, 8); return d;
}

__device__ __forceinline__ unsigned cvt_tf32(float x) {
    unsigned r;
    asm("cvt.rna.tf32.f32 %0, %1;" : "=r"(r) : "f"(x));
    return r;
}

// d += A(tf32) * B(tf32), m16n8k8, A row-major, B col-major, fp32 accum.
__device__ __forceinline__ void mma_tf32(float c[4],
                                         unsigned a0, unsigned a1, unsigned a2, unsigned a3,
                                         unsigned b0, unsigned b1) {
    asm("mma.sync.aligned.m16n8k8.row.col.f32.tf32.tf32.f32 "
        "{%0,%1,%2,%3}, {%4,%5,%6,%7}, {%8,%9}, {%0,%1,%2,%3};"
        : "+f"(c[0]), "+f"(c[1]), "+f"(c[2]), "+f"(c[3])
        : "r"(a0), "r"(a1), "r"(a2), "r"(a3), "r"(b0), "r"(b1));
}

__global__ void zero_kernel(int n4) {
    int i = blockIdx.x * blockDim.x + threadIdx.x;
    if (i < n4) {
        reinterpret_cast<float4*>(g_summ)[i] = make_float4(0.f, 0.f, 0.f, 0.f);
    }
}

extern __shared__ float smem_f[];

// ---------------------------------------------------------------------------
// phi kernel (tensor cores, 3xTF32): per-CTA 128x64 tile.
//   H1 = relu(X @ W1 + b1); H2 = H1 @ W2 + b2; segment-sum H2 -> g_summ.
// 8 warps; warp w owns rows m0 = 16*w (A-fragments private per warp -> no
// inter-layer sync). Weights pre-split (w32, dw) in smem; activations split
// on the fly. Epilogue: dump H2 to smem, sorted-run scan, few atomics.
// ---------------------------------------------------------------------------
__global__ __launch_bounds__(256, 2)
void phi_kernel(const float* __restrict__ nb,
                const float* __restrict__ w1, const float* __restrict__ b1,
                const float* __restrict__ w2, const float* __restrict__ b2,
                const int*   __restrict__ seg,
                int nrows)
{
    float* Xs   = smem_f;                        // 128*68 = 8704 (X -> H1 -> H2)
    float* W1h  = Xs  + TILE * XS_STR;           // 64*72 = 4608 (tf32-rounded W1)
    float* W1l  = W1h + K_DIM * WS_STR;          // 4608 (delta W1, tf32)
    float* W2h  = W1l + K_DIM * WS_STR;          // 4608
    float* W2l  = W2h + K_DIM * WS_STR;          // 4608
    float* b1s  = W2l + K_DIM * WS_STR;          // 64
    float* b2s  = b1s + 64;                      // 64
    int*   segs = (int*)(b2s + 64);              // 128

    const int tid  = threadIdx.x;
    const int lane = tid & 31;
    const int warp = tid >> 5;

    // ---- stage + split weights ----
    #pragma unroll 4
    for (int i = tid; i < K_DIM * K_DIM; i += 256) {
        int r = i >> 6, c = i & 63;
        float v1 = w1[i], v2 = w2[i];
        unsigned h1 = cvt_tf32(v1), h2 = cvt_tf32(v2);
        W1h[r * WS_STR + c] = __uint_as_float(h1);
        W2h[r * WS_STR + c] = __uint_as_float(h2);
        W1l[r * WS_STR + c] = __uint_as_float(cvt_tf32(v1 - __uint_as_float(h1)));
        W2l[r * WS_STR + c] = __uint_as_float(cvt_tf32(v2 - __uint_as_float(h2)));
    }
    if (tid < 64) { b1s[tid] = b1[tid]; b2s[tid] = b2[tid]; }

    const int base = blockIdx.x * TILE;

    // ---- load X tile row-major (stride 68), zero-pad OOB rows ----
    {
        const float4* s4 = reinterpret_cast<const float4*>(nb + (long long)base * K_DIM);
        #pragma unroll
        for (int i = tid; i < TILE * K_DIM / 4; i += 256) {
            int idx = i * 4;
            int r = idx >> 6, c = idx & 63;
            float4 v = (base + r < nrows) ? s4[i] : make_float4(0.f, 0.f, 0.f, 0.f);
            *reinterpret_cast<float4*>(&Xs[r * XS_STR + c]) = v;
        }
    }
    if (tid < TILE) segs[tid] = (base + tid < nrows) ? seg[base + tid] : -1;
    __syncthreads();

    const int m0 = warp * 16;
    const int g  = lane >> 2;        // groupID
    const int q  = lane & 3;         // threadID in group

    float acc[8][4];

    // =================== Layer 1 ===================
    #pragma unroll
    for (int j = 0; j < 8; j++) {
        float bv0 = b1s[8 * j + 2 * q], bv1 = b1s[8 * j + 2 * q + 1];
        acc[j][0] = bv0; acc[j][1] = bv1; acc[j][2] = bv0; acc[j][3] = bv1;
    }
    #pragma unroll
    for (int kk = 0; kk < 8; kk++) {
        const int k0 = 8 * kk;
        float x0 = Xs[(m0 + g)     * XS_STR + k0 + q];
        float x1 = Xs[(m0 + g + 8) * XS_STR + k0 + q];
        float x2 = Xs[(m0 + g)     * XS_STR + k0 + q + 4];
        float x3 = Xs[(m0 + g + 8) * XS_STR + k0 + q + 4];
        unsigned a0 = cvt_tf32(x0), a1 = cvt_tf32(x1), a2 = cvt_tf32(x2), a3 = cvt_tf32(x3);
        unsigned d0 = cvt_tf32(x0 - __uint_as_float(a0));
        unsigned d1 = cvt_tf32(x1 - __uint_as_float(a1));
        unsigned d2 = cvt_tf32(x2 - __uint_as_float(a2));
        unsigned d3 = cvt_tf32(x3 - __uint_as_float(a3));
        const int krow = k0 + q;
        #pragma unroll
        for (int j = 0; j < 8; j++) {
            const int ncol = 8 * j + g;
            unsigned bh0 = __float_as_uint(W1h[krow * WS_STR + ncol]);
            unsigned bh1 = __float_as_uint(W1h[(krow + 4) * WS_STR + ncol]);
            unsigned bl0 = __float_as_uint(W1l[krow * WS_STR + ncol]);
            unsigned bl1 = __float_as_uint(W1l[(krow + 4) * WS_STR + ncol]);
            mma_tf32(acc[j], a0, a1, a2, a3, bh0, bh1);
            mma_tf32(acc[j], d0, d1, d2, d3, bh0, bh1);
            mma_tf32(acc[j], a0, a1, a2, a3, bl0, bl1);
        }
    }
    // relu -> overwrite own rows of Xs with H1 (no sync needed: rows private)
    #pragma unroll
    for (int j = 0; j < 8; j++) {
        float2 lo = make_float2(fmaxf(acc[j][0], 0.f), fmaxf(acc[j][1], 0.f));
        float2 hi = make_float2(fmaxf(acc[j][2], 0.f), fmaxf(acc[j][3], 0.f));
        *reinterpret_cast<float2*>(&Xs[(m0 + g)     * XS_STR + 8 * j + 2 * q]) = lo;
        *reinterpret_cast<float2*>(&Xs[(m0 + g + 8) * XS_STR + 8 * j + 2 * q]) = hi;
    }
    __syncwarp();

    // =================== Layer 2 ===================
    #pragma unroll
    for (int j = 0; j < 8; j++) {
        float bv0 = b2s[8 * j + 2 * q], bv1 = b2s[8 * j + 2 * q + 1];
        acc[j][0] = bv0; acc[j][1] = bv1; acc[j][2] = bv0; acc[j][3] = bv1;
    }
    #pragma unroll
    for (int kk = 0; kk < 8; kk++) {
        const int k0 = 8 * kk;
        float x0 = Xs[(m0 + g)     * XS_STR + k0 + q];
        float x1 = Xs[(m0 + g + 8) * XS_STR + k0 + q];
        float x2 = Xs[(m0 + g)     * XS_STR + k0 + q + 4];
        float x3 = Xs[(m0 + g + 8) * XS_STR + k0 + q + 4];
        unsigned a0 = cvt_tf32(x0), a1 = cvt_tf32(x1), a2 = cvt_tf32(x2), a3 = cvt_tf32(x3);
        unsigned d0 = cvt_tf32(x0 - __uint_as_float(a0));
        unsigned d1 = cvt_tf32(x1 - __uint_as_float(a1));
        unsigned d2 = cvt_tf32(x2 - __uint_as_float(a2));
        unsigned d3 = cvt_tf32(x3 - __uint_as_float(a3));
        const int krow = k0 + q;
        #pragma unroll
        for (int j = 0; j < 8; j++) {
            const int ncol = 8 * j + g;
            unsigned bh0 = __float_as_uint(W2h[krow * WS_STR + ncol]);
            unsigned bh1 = __float_as_uint(W2h[(krow + 4) * WS_STR + ncol]);
            unsigned bl0 = __float_as_uint(W2l[krow * WS_STR + ncol]);
            unsigned bl1 = __float_as_uint(W2l[(krow + 4) * WS_STR + ncol]);
            mma_tf32(acc[j], a0, a1, a2, a3, bh0, bh1);
            mma_tf32(acc[j], d0, d1, d2, d3, bh0, bh1);
            mma_tf32(acc[j], a0, a1, a2, a3, bl0, bl1);
        }
    }
    __syncwarp();
    // dump H2 into Xs (own rows)
    #pragma unroll
    for (int j = 0; j < 8; j++) {
        *reinterpret_cast<float2*>(&Xs[(m0 + g)     * XS_STR + 8 * j + 2 * q]) =
            make_float2(acc[j][0], acc[j][1]);
        *reinterpret_cast<float2*>(&Xs[(m0 + g + 8) * XS_STR + 8 * j + 2 * q]) =
            make_float2(acc[j][2], acc[j][3]);
    }
    __syncthreads();

    // ---- segment reduction: sorted-run scan over 32-row blocks ----
    {
        const int col = tid & 63;
        const int rb  = tid >> 6;          // 0..3
        const int r0  = rb * 32;
        int cur = -1;
        float s = 0.f;
        #pragma unroll 8
        for (int i = 0; i < 32; i++) {
            int sid = segs[r0 + i];
            float v = Xs[(r0 + i) * XS_STR + col];
            if (sid == cur) { s += v; }
            else {
                if (cur >= 0) atomicAdd(&g_summ[cur * K_DIM + col], s);
                cur = sid; s = v;
            }
        }
        if (cur >= 0) atomicAdd(&g_summ[cur * K_DIM + col], s);
    }
}

// ---------------------------------------------------------------------------
// rho kernel (unchanged f32x2 path; ~3% of total work)
// ---------------------------------------------------------------------------
__device__ __forceinline__ int sw_off(int c, int ru) {
    return c * XT_STR + (((ru) ^ ((c >> 2) & 7)) << 2);
}

__device__ __forceinline__ void load_tile_T(const float* __restrict__ src,
                                            float* tT, int base, int nrows, int tid)
{
    const float4* s4 = reinterpret_cast<const float4*>(src + (long long)base * K_DIM);
    const int b = tid & 15;
    #pragma unroll
    for (int it = 0; it < 2; it++) {
        const int a = ((tid >> 4) << 1) + it;
        const int grow = base + 4 * a;
        float r[4][4];
        #pragma unroll
        for (int i = 0; i < 4; i++) {
            float4 v = (grow + i < nrows) ? s4[(4 * a + i) * 16 + b]
                                          : make_float4(0.f, 0.f, 0.f, 0.f);
            r[i][0] = v.x; r[i][1] = v.y; r[i][2] = v.z; r[i][3] = v.w;
        }
        #pragma unroll
        for (int j = 0; j < 4; j++) {
            const int c = 4 * b + j;
            float4 v = make_float4(r[0][j], r[1][j], r[2][j], r[3][j]);
            *reinterpret_cast<float4*>(&tT[sw_off(c, a)]) = v;
        }
    }
}

__device__ __forceinline__ void mma_tile(const float* xT, const float* w,
                                         int ty, int tx, float2 acc[4][4])
{
    const int col0 = tx * 4;
    #pragma unroll 4
    for (int k = 0; k < K_DIM; k++) {
        const int sk = (k >> 2) & 7;
        float4 a0 = *reinterpret_cast<const float4*>(&xT[k * XT_STR + (((2 * ty)     ^ sk) << 2)]);
        float4 a1 = *reinterpret_cast<const float4*>(&xT[k * XT_STR + (((2 * ty + 1) ^ sk) << 2)]);
        float4 wv = *reinterpret_cast<const float4*>(&w[k * K_DIM + col0]);
        float2 pr[4] = { make_float2(a0.x, a0.y), make_float2(a0.z, a0.w),
                         make_float2(a1.x, a1.y), make_float2(a1.z, a1.w) };
        float wa[4] = { wv.x, wv.y, wv.z, wv.w };
        #pragma unroll
        for (int c = 0; c < 4; c++) {
            float2 wb = make_float2(wa[c], wa[c]);
            #pragma unroll
            for (int p = 0; p < 4; p++) acc[p][c] = ffma2(pr[p], wb, acc[p][c]);
        }
    }
}

__device__ __forceinline__ void store_relu_T(float* hT, int ty, int tx, float2 acc[4][4])
{
    const int col0 = tx * 4;
    #pragma unroll
    for (int c = 0; c < 4; c++) {
        const int col = col0 + c;
        float4 lo = make_float4(fmaxf(acc[0][c].x, 0.f), fmaxf(acc[0][c].y, 0.f),
                                fmaxf(acc[1][c].x, 0.f), fmaxf(acc[1][c].y, 0.f));
        float4 hi = make_float4(fmaxf(acc[2][c].x, 0.f), fmaxf(acc[2][c].y, 0.f),
                                fmaxf(acc[3][c].x, 0.f), fmaxf(acc[3][c].y, 0.f));
        *reinterpret_cast<float4*>(&hT[sw_off(col, 2 * ty)])     = lo;
        *reinterpret_cast<float4*>(&hT[sw_off(col, 2 * ty + 1)]) = hi;
    }
}

__global__ __launch_bounds__(256, 2)
void rho_kernel(const float* __restrict__ w1, const float* __restrict__ b1,
                const float* __restrict__ w2, const float* __restrict__ b2,
                float* __restrict__ out, int nAgents)
{
    float* w1s = smem_f;
    float* xT  = w1s + 4096;
    float* hT  = xT  + 64 * XT_STR;
    float* b1s = hT  + 64 * XT_STR;
    float* w2b = b1s + 64;
    float* b2b = w2b + 128;

    const int tid = threadIdx.x;

    #pragma unroll 4
    for (int i = tid; i < 4096; i += 256) w1s[i] = w1[i];
    if (tid < 64)  b1s[tid] = b1[tid];
    if (tid < 128) w2b[tid] = w2[tid];
    if (tid < 2)   b2b[tid] = b2[tid];

    const int base = blockIdx.x * TILE;
    load_tile_T(g_summ, xT, base, nAgents, tid);
    __syncthreads();

    const int tx = tid & 15;
    const int ty = tid >> 4;
    const int col0 = tx * 4;

    float2 acc[4][4];
    #pragma unroll
    for (int c = 0; c < 4; c++) {
        float bv = b1s[col0 + c];
        #pragma unroll
        for (int p = 0; p < 4; p++) acc[p][c] = make_float2(bv, bv);
    }
    mma_tile(xT, w1s, ty, tx, acc);
    store_relu_T(hT, ty, tx, acc);
    __syncthreads();

    int r = tid >> 1;
    int c = tid & 1;
    if (base + r < nAgents) {
        float s = b2b[c];
        #pragma unroll 8
        for (int k = 0; k < K_DIM; k++) {
            int sk = (k >> 2) & 7;
            float hv = hT[k * XT_STR + ((((r >> 2) ^ sk) << 2)) + (r & 3)];
            s = fmaf(hv, w2b[k * 2 + c], s);
        }
        out[(base + r) * 2 + c] = s;
    }
}

// ---------------------------------------------------------------------------
extern "C" void kernel_launch(void* const* d_in, const int* in_sizes, int n_in,
                              void* d_out, int out_size)
{
    const float* neighbors = (const float*)d_in[0];
    const float* phi_w1    = (const float*)d_in[1];
    const float* phi_b1    = (const float*)d_in[2];
    const float* phi_w2    = (const float*)d_in[3];
    const float* phi_b2    = (const float*)d_in[4];
    const float* rho_w1    = (const float*)d_in[5];
    const float* rho_b1    = (const float*)d_in[6];
    const float* rho_w2    = (const float*)d_in[7];
    const float* rho_b2    = (const float*)d_in[8];
    const int*   seg       = (const int*)d_in[9];
    float* out = (float*)d_out;

    const int nN = in_sizes[9];
    const int nA = out_size / 2;

    const int PHI_SMEM = (TILE * XS_STR + 4 * K_DIM * WS_STR + 64 + 64 + 128) * 4; // 109568
    const int RHO_SMEM = (4096 + 64 * XT_STR + 64 * XT_STR + 64 + 128 + 2) * 4;

    cudaFuncSetAttribute(phi_kernel, cudaFuncAttributeMaxDynamicSharedMemorySize, PHI_SMEM);
    cudaFuncSetAttribute(rho_kernel, cudaFuncAttributeMaxDynamicSharedMemorySize, RHO_SMEM);

    const int n4 = MAX_AGENTS * K_DIM / 4;
    zero_kernel<<<(n4 + 255) / 256, 256>>>(n4);

    const int phi_blocks = (nN + TILE - 1) / TILE;
    phi_kernel<<<phi_blocks, 256, PHI_SMEM>>>(neighbors, phi_w1, phi_b1, phi_w2, phi_b2, seg, nN);

    const int rho_blocks = (nA + TILE - 1) / TILE;
    rho_kernel<<<rho_blocks, 256, RHO_SMEM>>>(rho_w1, rho_b1, rho_w2, rho_b2, out, nA);
}